// round 1
// baseline (speedup 1.0000x reference)
#include <cuda_runtime.h>
#include <math.h>

#define H 128
#define MAXN 100000
#define MAXE 500000
#define BN_EPS 1e-5f

// ---------------- scratch (device globals: no allocation allowed) -------------
__device__ __align__(16) float g_hu[(size_t)MAXN * H];
__device__ __align__(16) float g_hr[(size_t)MAXN * H];
__device__ __align__(16) float g_agg[(size_t)MAXN * H];
__device__ __align__(16) float g_tu[(size_t)MAXN * H];
__device__ __align__(16) float g_tr[(size_t)MAXN * H];
__device__ __align__(16) float g_cu[MAXN];   // becomes 1/max(cnt,1)
__device__ __align__(16) float g_cr[MAXN];

// ---------------- small utility kernels --------------------------------------
__global__ void zero_kernel(float* __restrict__ p, int n4) {
    int i = blockIdx.x * blockDim.x + threadIdx.x;
    if (i < n4) ((float4*)p)[i] = make_float4(0.f, 0.f, 0.f, 0.f);
}

__global__ void count_kernel(const int* __restrict__ dst, int E, float* __restrict__ cnt) {
    int i = blockIdx.x * blockDim.x + threadIdx.x;
    if (i < E) atomicAdd(&cnt[dst[i]], 1.0f);
}

__global__ void inv_kernel(float* __restrict__ c, int n) {
    int i = blockIdx.x * blockDim.x + threadIdx.x;
    if (i < n) c[i] = 1.0f / fmaxf(c[i], 1.0f);
}

// y[n,H] = x[n,32] @ W[32,H] + b
__global__ void proj_kernel(const float* __restrict__ x, const float* __restrict__ W,
                            const float* __restrict__ b, float* __restrict__ y, int n) {
    int i = blockIdx.x * blockDim.x + threadIdx.x;
    if (i >= n * H) return;
    int row = i >> 7;
    int c = i & (H - 1);
    const float* xr = x + (size_t)row * 32;
    float acc = b[c];
#pragma unroll
    for (int k = 0; k < 32; k++) acc = fmaf(xr[k], W[k * H + c], acc);
    y[i] = acc;
}

// agg[dst] += hsrc[src]   (one thread per (edge, 4-channel group))
__global__ void scatter_kernel(const float* __restrict__ hsrc, const int* __restrict__ srcI,
                               const int* __restrict__ dstI, float* __restrict__ agg, int E) {
    int t = blockIdx.x * blockDim.x + threadIdx.x;
    int e = t >> 5;
    int j = t & 31;
    if (e >= E) return;
    int s = srcI[e];
    int d = dstI[e];
    float4 v = ((const float4*)(hsrc + (size_t)s * H))[j];
    float* p = agg + (size_t)d * H + j * 4;
    atomicAdd(p + 0, v.x);
    atomicAdd(p + 1, v.y);
    atomicAdd(p + 2, v.z);
    atomicAdd(p + 3, v.w);
}

// out[M,H] = (rowscale(A) @ W1) + (B @ W2) + bias
// persistent grid; W1,W2 fully resident in SMEM; 32-row tiles; 4x4 register tile
__global__ void gemm2_kernel(const float* __restrict__ A, const float* __restrict__ invc,
                             const float* __restrict__ B, const float* __restrict__ W1,
                             const float* __restrict__ W2, const float* __restrict__ bias,
                             float* __restrict__ out, int M) {
    extern __shared__ float sm[];
    float* sW1 = sm;                 // H*H
    float* sW2 = sm + H * H;         // H*H
    float* sA = sW2 + H * H;         // 32*H
    float* sB = sA + 32 * H;         // 32*H
    float* sbias = sB + 32 * H;      // H
    int tid = threadIdx.x;

    for (int i = tid; i < H * H / 4; i += 256) {
        ((float4*)sW1)[i] = ((const float4*)W1)[i];
        ((float4*)sW2)[i] = ((const float4*)W2)[i];
    }
    if (tid < H) sbias[tid] = bias[tid];
    __syncthreads();

    int tc = tid & 31;          // column group: c0 = tc*4
    int te = tid >> 5;          // row group:    e0 = te*4
    int c0 = tc * 4;
    int e0 = te * 4;
    int numTiles = M / 32;

    for (int tile = blockIdx.x; tile < numTiles; tile += gridDim.x) {
        int row0 = tile * 32;
        // load tiles: warp te handles rows te*4 .. te*4+3
#pragma unroll
        for (int j = 0; j < 4; j++) {
            int r = te * 4 + j;
            float sc = invc[row0 + r];
            float4 a = ((const float4*)(A + (size_t)(row0 + r) * H))[tc];
            a.x *= sc; a.y *= sc; a.z *= sc; a.w *= sc;
            ((float4*)(sA + r * H))[tc] = a;
            ((float4*)(sB + r * H))[tc] = ((const float4*)(B + (size_t)(row0 + r) * H))[tc];
        }
        __syncthreads();

        float acc[4][4];
        {
            float4 bb = *(const float4*)(sbias + c0);
#pragma unroll
            for (int jr = 0; jr < 4; jr++) {
                acc[jr][0] = bb.x; acc[jr][1] = bb.y; acc[jr][2] = bb.z; acc[jr][3] = bb.w;
            }
        }
        const float* r0 = sA + (e0 + 0) * H;
        const float* r1 = sA + (e0 + 1) * H;
        const float* r2 = sA + (e0 + 2) * H;
        const float* r3 = sA + (e0 + 3) * H;
        for (int k = 0; k < H; k += 4) {
            float4 x0 = *(const float4*)(r0 + k);
            float4 x1 = *(const float4*)(r1 + k);
            float4 x2 = *(const float4*)(r2 + k);
            float4 x3 = *(const float4*)(r3 + k);
#pragma unroll
            for (int kk = 0; kk < 4; kk++) {
                float4 w = *(const float4*)(sW1 + (k + kk) * H + c0);
                float a0 = ((const float*)&x0)[kk];
                float a1 = ((const float*)&x1)[kk];
                float a2 = ((const float*)&x2)[kk];
                float a3 = ((const float*)&x3)[kk];
                acc[0][0] = fmaf(a0, w.x, acc[0][0]); acc[0][1] = fmaf(a0, w.y, acc[0][1]);
                acc[0][2] = fmaf(a0, w.z, acc[0][2]); acc[0][3] = fmaf(a0, w.w, acc[0][3]);
                acc[1][0] = fmaf(a1, w.x, acc[1][0]); acc[1][1] = fmaf(a1, w.y, acc[1][1]);
                acc[1][2] = fmaf(a1, w.z, acc[1][2]); acc[1][3] = fmaf(a1, w.w, acc[1][3]);
                acc[2][0] = fmaf(a2, w.x, acc[2][0]); acc[2][1] = fmaf(a2, w.y, acc[2][1]);
                acc[2][2] = fmaf(a2, w.z, acc[2][2]); acc[2][3] = fmaf(a2, w.w, acc[2][3]);
                acc[3][0] = fmaf(a3, w.x, acc[3][0]); acc[3][1] = fmaf(a3, w.y, acc[3][1]);
                acc[3][2] = fmaf(a3, w.z, acc[3][2]); acc[3][3] = fmaf(a3, w.w, acc[3][3]);
            }
        }
        const float* q0 = sB + (e0 + 0) * H;
        const float* q1 = sB + (e0 + 1) * H;
        const float* q2 = sB + (e0 + 2) * H;
        const float* q3 = sB + (e0 + 3) * H;
        for (int k = 0; k < H; k += 4) {
            float4 x0 = *(const float4*)(q0 + k);
            float4 x1 = *(const float4*)(q1 + k);
            float4 x2 = *(const float4*)(q2 + k);
            float4 x3 = *(const float4*)(q3 + k);
#pragma unroll
            for (int kk = 0; kk < 4; kk++) {
                float4 w = *(const float4*)(sW2 + (k + kk) * H + c0);
                float a0 = ((const float*)&x0)[kk];
                float a1 = ((const float*)&x1)[kk];
                float a2 = ((const float*)&x2)[kk];
                float a3 = ((const float*)&x3)[kk];
                acc[0][0] = fmaf(a0, w.x, acc[0][0]); acc[0][1] = fmaf(a0, w.y, acc[0][1]);
                acc[0][2] = fmaf(a0, w.z, acc[0][2]); acc[0][3] = fmaf(a0, w.w, acc[0][3]);
                acc[1][0] = fmaf(a1, w.x, acc[1][0]); acc[1][1] = fmaf(a1, w.y, acc[1][1]);
                acc[1][2] = fmaf(a1, w.z, acc[1][2]); acc[1][3] = fmaf(a1, w.w, acc[1][3]);
                acc[2][0] = fmaf(a2, w.x, acc[2][0]); acc[2][1] = fmaf(a2, w.y, acc[2][1]);
                acc[2][2] = fmaf(a2, w.z, acc[2][2]); acc[2][3] = fmaf(a2, w.w, acc[2][3]);
                acc[3][0] = fmaf(a3, w.x, acc[3][0]); acc[3][1] = fmaf(a3, w.y, acc[3][1]);
                acc[3][2] = fmaf(a3, w.z, acc[3][2]); acc[3][3] = fmaf(a3, w.w, acc[3][3]);
            }
        }
#pragma unroll
        for (int jr = 0; jr < 4; jr++) {
            float4 o = make_float4(acc[jr][0], acc[jr][1], acc[jr][2], acc[jr][3]);
            ((float4*)(out + (size_t)(row0 + e0 + jr) * H))[tc] = o;
        }
        __syncthreads();
    }
}

// h = relu(bn(tmp)) + h
__global__ void update_kernel(float* __restrict__ h, const float* __restrict__ t,
                              const float* __restrict__ g, const float* __restrict__ bb,
                              const float* __restrict__ m, const float* __restrict__ v, int n) {
    int i = blockIdx.x * blockDim.x + threadIdx.x;   // n*H/4 threads
    if (i >= n * (H / 4)) return;
    int c0 = (i & 31) * 4;
    float4 tv = ((const float4*)t)[i];
    float4 hv = ((const float4*)h)[i];
    float r[4] = {tv.x, tv.y, tv.z, tv.w};
    float hvv[4] = {hv.x, hv.y, hv.z, hv.w};
#pragma unroll
    for (int j = 0; j < 4; j++) {
        int c = c0 + j;
        float s = g[c] * rsqrtf(v[c] + BN_EPS);
        float val = (r[j] - m[c]) * s + bb[c];
        r[j] = fmaxf(val, 0.0f) + hvv[j];
    }
    ((float4*)h)[i] = make_float4(r[0], r[1], r[2], r[3]);
}

// Fused edge predictor: per 32-edge tile, gather [src||dst||ea] (272),
// MLP 272->128 (+ReLU+BN) -> 64 (+ReLU) -> 1 (+sigmoid). All weights in SMEM.
__global__ void edgepred_kernel(const int* __restrict__ utSrc, const int* __restrict__ utDst,
                                const float* __restrict__ ea,
                                const float* __restrict__ W1, const float* __restrict__ b1,
                                const float* __restrict__ bng, const float* __restrict__ bnb,
                                const float* __restrict__ bnm, const float* __restrict__ bnv,
                                const float* __restrict__ W2, const float* __restrict__ b2,
                                const float* __restrict__ W3, const float* __restrict__ b3,
                                float* __restrict__ outp, int E) {
    extern __shared__ float sm[];
    float* sW1 = sm;                      // 272*128 = 34816
    float* sW2 = sW1 + 272 * H;           // 128*64  = 8192
    float* xs = sW2 + H * 64;             // 32*272  = 8704  (reused as h2 [32][65])
    float* h1 = xs + 32 * 272;            // 32*128  = 4096
    float* pb1 = h1 + 32 * H;             // 128
    float* ps1 = pb1 + H;                 // 128
    float* pt1 = ps1 + H;                 // 128
    float* pb2 = pt1 + H;                 // 64
    float* pW3 = pb2 + 64;                // 64
    float* pb3 = pW3 + 64;                // 1

    int tid = threadIdx.x;
    int lane = tid & 31;
    int w = tid >> 5;

    for (int i = tid; i < (272 * H) / 4; i += 256)
        ((float4*)sW1)[i] = ((const float4*)W1)[i];
    for (int i = tid; i < (H * 64) / 4; i += 256)
        ((float4*)sW2)[i] = ((const float4*)W2)[i];
    if (tid < H) {
        pb1[tid] = b1[tid];
        float s = bng[tid] * rsqrtf(bnv[tid] + BN_EPS);
        ps1[tid] = s;
        pt1[tid] = bnb[tid] - bnm[tid] * s;
    } else if (tid < 192) {
        pb2[tid - 128] = b2[tid - 128];
    } else {
        pW3[tid - 192] = W3[tid - 192];
    }
    if (tid == 0) pb3[0] = b3[0];
    __syncthreads();

    int tc = tid & 31;      // layer1 col group
    int te = tid >> 5;      // layer1 edge group
    int c0 = tc * 4;
    int e0 = te * 4;
    int tc2 = tid & 15;     // layer2 col group
    int te2 = tid >> 4;     // layer2 edge group
    int cc0 = tc2 * 4;
    int ee0 = te2 * 2;

    int numTiles = E / 32;
    for (int tile = blockIdx.x; tile < numTiles; tile += gridDim.x) {
        int base = tile * 32;
        // gather: warp w loads edges w*4 .. w*4+3
#pragma unroll
        for (int i = 0; i < 4; i++) {
            int e = w * 4 + i;
            int eg = base + e;
            int s = utSrc[eg];
            int d = utDst[eg];
            float4 a = ((const float4*)(g_hu + (size_t)s * H))[lane];
            *(float4*)(xs + e * 272 + lane * 4) = a;
            float4 bv = ((const float4*)(g_hr + (size_t)d * H))[lane];
            *(float4*)(xs + e * 272 + 128 + lane * 4) = bv;
            if (lane < 4) {
                float4 ev = ((const float4*)(ea + (size_t)eg * 16))[lane];
                *(float4*)(xs + e * 272 + 256 + lane * 4) = ev;
            }
        }
        __syncthreads();

        // layer 1: 32x128 outputs, K=272
        float acc[4][4];
        {
            float4 bb = *(const float4*)(pb1 + c0);
#pragma unroll
            for (int jr = 0; jr < 4; jr++) {
                acc[jr][0] = bb.x; acc[jr][1] = bb.y; acc[jr][2] = bb.z; acc[jr][3] = bb.w;
            }
        }
        const float* r0 = xs + (e0 + 0) * 272;
        const float* r1 = xs + (e0 + 1) * 272;
        const float* r2 = xs + (e0 + 2) * 272;
        const float* r3 = xs + (e0 + 3) * 272;
        for (int k = 0; k < 272; k += 4) {
            float4 x0 = *(const float4*)(r0 + k);
            float4 x1 = *(const float4*)(r1 + k);
            float4 x2 = *(const float4*)(r2 + k);
            float4 x3 = *(const float4*)(r3 + k);
#pragma unroll
            for (int kk = 0; kk < 4; kk++) {
                float4 wv = *(const float4*)(sW1 + (k + kk) * H + c0);
                float a0 = ((const float*)&x0)[kk];
                float a1 = ((const float*)&x1)[kk];
                float a2 = ((const float*)&x2)[kk];
                float a3 = ((const float*)&x3)[kk];
                acc[0][0] = fmaf(a0, wv.x, acc[0][0]); acc[0][1] = fmaf(a0, wv.y, acc[0][1]);
                acc[0][2] = fmaf(a0, wv.z, acc[0][2]); acc[0][3] = fmaf(a0, wv.w, acc[0][3]);
                acc[1][0] = fmaf(a1, wv.x, acc[1][0]); acc[1][1] = fmaf(a1, wv.y, acc[1][1]);
                acc[1][2] = fmaf(a1, wv.z, acc[1][2]); acc[1][3] = fmaf(a1, wv.w, acc[1][3]);
                acc[2][0] = fmaf(a2, wv.x, acc[2][0]); acc[2][1] = fmaf(a2, wv.y, acc[2][1]);
                acc[2][2] = fmaf(a2, wv.z, acc[2][2]); acc[2][3] = fmaf(a2, wv.w, acc[2][3]);
                acc[3][0] = fmaf(a3, wv.x, acc[3][0]); acc[3][1] = fmaf(a3, wv.y, acc[3][1]);
                acc[3][2] = fmaf(a3, wv.z, acc[3][2]); acc[3][3] = fmaf(a3, wv.w, acc[3][3]);
            }
        }
        // relu -> BN, write h1
#pragma unroll
        for (int jr = 0; jr < 4; jr++) {
            float o[4];
#pragma unroll
            for (int jc = 0; jc < 4; jc++) {
                float z = fmaxf(acc[jr][jc], 0.0f);
                o[jc] = z * ps1[c0 + jc] + pt1[c0 + jc];
            }
            *(float4*)(h1 + (e0 + jr) * H + c0) = make_float4(o[0], o[1], o[2], o[3]);
        }
        __syncthreads();

        // layer 2: 32x64 outputs, K=128 ; h2 overwrites xs (stride 65)
        float* h2 = xs;
        {
            float a2r[2][4];
            float4 bb = *(const float4*)(pb2 + cc0);
#pragma unroll
            for (int jr = 0; jr < 2; jr++) {
                a2r[jr][0] = bb.x; a2r[jr][1] = bb.y; a2r[jr][2] = bb.z; a2r[jr][3] = bb.w;
            }
            const float* hA = h1 + (ee0 + 0) * H;
            const float* hB = h1 + (ee0 + 1) * H;
            for (int k = 0; k < H; k += 4) {
                float4 xA = *(const float4*)(hA + k);
                float4 xB = *(const float4*)(hB + k);
#pragma unroll
                for (int kk = 0; kk < 4; kk++) {
                    float4 wv = *(const float4*)(sW2 + (k + kk) * 64 + cc0);
                    float aA = ((const float*)&xA)[kk];
                    float aB = ((const float*)&xB)[kk];
                    a2r[0][0] = fmaf(aA, wv.x, a2r[0][0]); a2r[0][1] = fmaf(aA, wv.y, a2r[0][1]);
                    a2r[0][2] = fmaf(aA, wv.z, a2r[0][2]); a2r[0][3] = fmaf(aA, wv.w, a2r[0][3]);
                    a2r[1][0] = fmaf(aB, wv.x, a2r[1][0]); a2r[1][1] = fmaf(aB, wv.y, a2r[1][1]);
                    a2r[1][2] = fmaf(aB, wv.z, a2r[1][2]); a2r[1][3] = fmaf(aB, wv.w, a2r[1][3]);
                }
            }
#pragma unroll
            for (int jr = 0; jr < 2; jr++)
#pragma unroll
                for (int jc = 0; jc < 4; jc++)
                    h2[(ee0 + jr) * 65 + cc0 + jc] = fmaxf(a2r[jr][jc], 0.0f);
        }
        __syncthreads();

        // layer 3 + sigmoid
        if (tid < 32) {
            int e = tid;
            float a = pb3[0];
#pragma unroll
            for (int k = 0; k < 64; k++) a = fmaf(h2[e * 65 + k], pW3[k], a);
            outp[base + e] = 1.0f / (1.0f + expf(-a));
        }
        __syncthreads();
    }
}

// ------------------------------- host ----------------------------------------
extern "C" void kernel_launch(void* const* d_in, const int* in_sizes, int n_in,
                              void* d_out, int out_size) {
    const float* x_user = (const float*)d_in[0];
    const float* x_recip = (const float*)d_in[1];
    const float* edge_attr = (const float*)d_in[2];
    const int* ei_ut = (const int*)d_in[3];
    const int* ei_ru = (const int*)d_in[4];
    const float* proj_uW = (const float*)d_in[5];
    const float* proj_ub = (const float*)d_in[6];
    const float* proj_rW = (const float*)d_in[7];
    const float* proj_rb = (const float*)d_in[8];
    const float* sage_Wl = (const float*)d_in[9];
    const float* sage_bl = (const float*)d_in[10];
    const float* sage_Wr = (const float*)d_in[11];
    const float* bn_g = (const float*)d_in[12];
    const float* bn_b = (const float*)d_in[13];
    const float* bn_m = (const float*)d_in[14];
    const float* bn_v = (const float*)d_in[15];
    const float* ep_W1 = (const float*)d_in[16];
    const float* ep_b1 = (const float*)d_in[17];
    const float* ep_bng = (const float*)d_in[18];
    const float* ep_bnb = (const float*)d_in[19];
    const float* ep_bnm = (const float*)d_in[20];
    const float* ep_bnv = (const float*)d_in[21];
    const float* ep_W2 = (const float*)d_in[22];
    const float* ep_b2 = (const float*)d_in[23];
    const float* ep_W3 = (const float*)d_in[24];
    const float* ep_b3 = (const float*)d_in[25];
    float* out = (float*)d_out;

    int Nu = in_sizes[0] / 32;
    int Nr = in_sizes[1] / 32;
    int E = in_sizes[3] / 2;

    const int* utSrc = ei_ut;
    const int* utDst = ei_ut + E;
    const int* ruSrc = ei_ru;
    const int* ruDst = ei_ru + E;

    float* hu; cudaGetSymbolAddress((void**)&hu, g_hu);
    float* hr; cudaGetSymbolAddress((void**)&hr, g_hr);
    float* agg; cudaGetSymbolAddress((void**)&agg, g_agg);
    float* tu; cudaGetSymbolAddress((void**)&tu, g_tu);
    float* tr; cudaGetSymbolAddress((void**)&tr, g_tr);
    float* cu; cudaGetSymbolAddress((void**)&cu, g_cu);
    float* cr; cudaGetSymbolAddress((void**)&cr, g_cr);

    const int G2_SMEM = (H * H * 2 + 32 * H * 2 + H) * 4;                 // 164352
    const int EP_SMEM = (272 * H + H * 64 + 32 * 272 + 32 * H + 3 * H + 64 + 64 + 1) * 4;
    cudaFuncSetAttribute(gemm2_kernel, cudaFuncAttributeMaxDynamicSharedMemorySize, G2_SMEM);
    cudaFuncSetAttribute(edgepred_kernel, cudaFuncAttributeMaxDynamicSharedMemorySize, EP_SMEM);

    const int T = 256;
    // counts (reused by both layers)
    zero_kernel<<<(Nu / 4 + T - 1) / T, T>>>(cu, Nu / 4);
    zero_kernel<<<(Nr / 4 + T - 1) / T, T>>>(cr, Nr / 4);
    count_kernel<<<(E + T - 1) / T, T>>>(ruDst, E, cu);
    count_kernel<<<(E + T - 1) / T, T>>>(utDst, E, cr);
    inv_kernel<<<(Nu + T - 1) / T, T>>>(cu, Nu);
    inv_kernel<<<(Nr + T - 1) / T, T>>>(cr, Nr);

    // input projections
    proj_kernel<<<(Nu * H + T - 1) / T, T>>>(x_user, proj_uW, proj_ub, hu, Nu);
    proj_kernel<<<(Nr * H + T - 1) / T, T>>>(x_recip, proj_rW, proj_rb, hr, Nr);

    const int GRID_P = 148;
    for (int i = 0; i < 2; i++) {
        // edge type 0: user -> recipient
        zero_kernel<<<(Nr * 32 + T - 1) / T, T>>>(agg, Nr * 32);
        scatter_kernel<<<(E * 32 + T - 1) / T, T>>>(hu, utSrc, utDst, agg, E);
        gemm2_kernel<<<GRID_P, T, G2_SMEM>>>(agg, cr, hr,
                                             sage_Wl + (size_t)(i * 2 + 0) * H * H,
                                             sage_Wr + (size_t)(i * 2 + 0) * H * H,
                                             sage_bl + (size_t)(i * 2 + 0) * H, tr, Nr);
        // edge type 1: recipient -> user
        zero_kernel<<<(Nu * 32 + T - 1) / T, T>>>(agg, Nu * 32);
        scatter_kernel<<<(E * 32 + T - 1) / T, T>>>(hr, ruSrc, ruDst, agg, E);
        gemm2_kernel<<<GRID_P, T, G2_SMEM>>>(agg, cu, hu,
                                             sage_Wl + (size_t)(i * 2 + 1) * H * H,
                                             sage_Wr + (size_t)(i * 2 + 1) * H * H,
                                             sage_bl + (size_t)(i * 2 + 1) * H, tu, Nu);
        // BN + ReLU + residual
        update_kernel<<<(Nu * 32 + T - 1) / T, T>>>(hu, tu,
                                                    bn_g + (i * 2 + 0) * H, bn_b + (i * 2 + 0) * H,
                                                    bn_m + (i * 2 + 0) * H, bn_v + (i * 2 + 0) * H, Nu);
        update_kernel<<<(Nr * 32 + T - 1) / T, T>>>(hr, tr,
                                                    bn_g + (i * 2 + 1) * H, bn_b + (i * 2 + 1) * H,
                                                    bn_m + (i * 2 + 1) * H, bn_v + (i * 2 + 1) * H, Nr);
    }

    edgepred_kernel<<<GRID_P, T, EP_SMEM>>>(utSrc, utDst, edge_attr,
                                            ep_W1, ep_b1, ep_bng, ep_bnb, ep_bnm, ep_bnv,
                                            ep_W2, ep_b2, ep_W3, ep_b3, out, E);
}

// round 3
// speedup vs baseline: 1.7598x; 1.7598x over previous
#include <cuda_runtime.h>
#include <math.h>

#define H 128
#define MAXN 100000
#define BN_EPS 1e-5f

// ---------------- scratch (device globals: no allocation allowed) -------------
__device__ __align__(16) float g_hu[(size_t)MAXN * H];
__device__ __align__(16) float g_hr[(size_t)MAXN * H];
__device__ __align__(16) float g_aggR[(size_t)MAXN * H];   // later reused as Pu
__device__ __align__(16) float g_aggU[(size_t)MAXN * H];   // later reused as Pr
__device__ __align__(16) float g_cu[MAXN];   // becomes 1/max(cnt,1)
__device__ __align__(16) float g_cr[MAXN];

// ---------------- small utility kernels --------------------------------------
__global__ void zero_kernel(float* __restrict__ p, int n4) {
    int i = blockIdx.x * blockDim.x + threadIdx.x;
    if (i < n4) ((float4*)p)[i] = make_float4(0.f, 0.f, 0.f, 0.f);
}

__global__ void count_kernel(const int* __restrict__ dst, int E, float* __restrict__ cnt) {
    int i = blockIdx.x * blockDim.x + threadIdx.x;
    if (i < E) atomicAdd(&cnt[dst[i]], 1.0f);
}

__global__ void inv_kernel(float* __restrict__ c, int n) {
    int i = blockIdx.x * blockDim.x + threadIdx.x;
    if (i < n) c[i] = 1.0f / fmaxf(c[i], 1.0f);
}

// y[n,H] = x[n,32] @ W[32,H] + b
__global__ void proj_kernel(const float* __restrict__ x, const float* __restrict__ W,
                            const float* __restrict__ b, float* __restrict__ y, int n) {
    int i = blockIdx.x * blockDim.x + threadIdx.x;
    if (i >= n * H) return;
    int row = i >> 7;
    int c = i & (H - 1);
    const float* xr = x + (size_t)row * 32;
    float acc = b[c];
#pragma unroll
    for (int k = 0; k < 32; k++) acc = fmaf(xr[k], W[k * H + c], acc);
    y[i] = acc;
}

// agg[dst] += hsrc[src]  using 128-bit vector reductions (sm_90+)
// 32 threads per edge, each handles one float4 group (covers all 128 channels)
__global__ void scatter_kernel(const float* __restrict__ hsrc, const int* __restrict__ srcI,
                               const int* __restrict__ dstI, float* __restrict__ agg, int E) {
    int t = blockIdx.x * blockDim.x + threadIdx.x;
    int e = t >> 5;
    int j = t & 31;
    if (e >= E) return;
    int s = srcI[e];
    int d = dstI[e];
    float4 v = ((const float4*)(hsrc + (size_t)s * H))[j];
    float* p = agg + (size_t)d * H + j * 4;
    asm volatile("red.global.add.v4.f32 [%0], {%1, %2, %3, %4};"
                 :: "l"(p), "f"(v.x), "f"(v.y), "f"(v.z), "f"(v.w) : "memory");
}

// In-place SAGE layer:  Bh = relu(bn( rowscale(A)@W1 + bias + Bh@W2 )) + Bh
// persistent grid; W1,W2 resident in SMEM; 64-row tiles; 8x4 register tile
__global__ void __launch_bounds__(256, 1)
gemm2_kernel(const float* __restrict__ A, const float* __restrict__ invc,
             float* __restrict__ Bh,
             const float* __restrict__ W1, const float* __restrict__ W2,
             const float* __restrict__ bias,
             const float* __restrict__ bg, const float* __restrict__ bb,
             const float* __restrict__ bm, const float* __restrict__ bv, int M) {
    extern __shared__ float sm[];
    float* sW1 = sm;                 // 16384
    float* sW2 = sm + 16384;         // 16384
    float* sA = sW2 + 16384;         // 64*H = 8192
    float* sB = sA + 8192;           // 8192
    float* sbias = sB + 8192;        // 128
    float* sS = sbias + 128;         // 128
    float* sT = sS + 128;            // 128
    int tid = threadIdx.x;

    for (int i = tid; i < 16384 / 4; i += 256) {
        ((float4*)sW1)[i] = ((const float4*)W1)[i];
        ((float4*)sW2)[i] = ((const float4*)W2)[i];
    }
    if (tid < 128) {
        sbias[tid] = bias[tid];
        float s = bg[tid] * rsqrtf(bv[tid] + BN_EPS);
        sS[tid] = s;
        sT[tid] = bb[tid] - bm[tid] * s;
    }
    __syncthreads();

    int tc = tid & 31;          // column group: c0 = tc*4
    int te = tid >> 5;          // warp -> 8 rows
    int c0 = tc * 4;
    int numTiles = (M + 63) >> 6;

    for (int tile = blockIdx.x; tile < numTiles; tile += gridDim.x) {
        int row0 = tile * 64;
#pragma unroll
        for (int j = 0; j < 8; j++) {
            int lr = te * 8 + j;
            int r = row0 + lr;
            if (r < M) {
                float sc = invc[r];
                float4 a = ((const float4*)(A + (size_t)r * H))[tc];
                a.x *= sc; a.y *= sc; a.z *= sc; a.w *= sc;
                ((float4*)(sA + lr * H))[tc] = a;
                ((float4*)(sB + lr * H))[tc] = ((const float4*)(Bh + (size_t)r * H))[tc];
            } else {
                ((float4*)(sA + lr * H))[tc] = make_float4(0.f, 0.f, 0.f, 0.f);
                ((float4*)(sB + lr * H))[tc] = make_float4(0.f, 0.f, 0.f, 0.f);
            }
        }
        __syncthreads();

        float acc[8][4];
        {
            float4 bbv = *(const float4*)(sbias + c0);
#pragma unroll
            for (int jr = 0; jr < 8; jr++) {
                acc[jr][0] = bbv.x; acc[jr][1] = bbv.y; acc[jr][2] = bbv.z; acc[jr][3] = bbv.w;
            }
        }
#pragma unroll
        for (int pass = 0; pass < 2; pass++) {
            const float* X = pass ? sB : sA;
            const float* W = pass ? sW2 : sW1;
            for (int k = 0; k < H; k += 4) {
                float4 x[8];
#pragma unroll
                for (int jr = 0; jr < 8; jr++)
                    x[jr] = *(const float4*)(X + (te * 8 + jr) * H + k);
#pragma unroll
                for (int kk = 0; kk < 4; kk++) {
                    float4 w = *(const float4*)(W + (k + kk) * H + c0);
#pragma unroll
                    for (int jr = 0; jr < 8; jr++) {
                        float a = ((const float*)&x[jr])[kk];
                        acc[jr][0] = fmaf(a, w.x, acc[jr][0]);
                        acc[jr][1] = fmaf(a, w.y, acc[jr][1]);
                        acc[jr][2] = fmaf(a, w.z, acc[jr][2]);
                        acc[jr][3] = fmaf(a, w.w, acc[jr][3]);
                    }
                }
            }
        }
        // epilogue: relu(bn(acc)) + h   (h row is in sB)
        {
            float4 sv = *(const float4*)(sS + c0);
            float4 tv = *(const float4*)(sT + c0);
#pragma unroll
            for (int jr = 0; jr < 8; jr++) {
                int lr = te * 8 + jr;
                int r = row0 + lr;
                if (r < M) {
                    float4 hb = *(const float4*)(sB + lr * H + c0);
                    float4 o;
                    o.x = fmaxf(acc[jr][0] * sv.x + tv.x, 0.f) + hb.x;
                    o.y = fmaxf(acc[jr][1] * sv.y + tv.y, 0.f) + hb.y;
                    o.z = fmaxf(acc[jr][2] * sv.z + tv.z, 0.f) + hb.z;
                    o.w = fmaxf(acc[jr][3] * sv.w + tv.w, 0.f) + hb.w;
                    ((float4*)(Bh + (size_t)r * H))[tc] = o;
                }
            }
        }
        __syncthreads();
    }
}

// out[M,128] = A[M,128] @ W[128,128]   (no bias) — for Pu/Pr precompute
__global__ void __launch_bounds__(256, 2)
gemm1_kernel(const float* __restrict__ A, const float* __restrict__ W,
             float* __restrict__ out, int M) {
    extern __shared__ float sm[];
    float* sW = sm;           // 16384
    float* sA = sm + 16384;   // 8192
    int tid = threadIdx.x;
    for (int i = tid; i < 16384 / 4; i += 256)
        ((float4*)sW)[i] = ((const float4*)W)[i];
    __syncthreads();

    int tc = tid & 31;
    int te = tid >> 5;
    int c0 = tc * 4;
    int numTiles = (M + 63) >> 6;

    for (int tile = blockIdx.x; tile < numTiles; tile += gridDim.x) {
        int row0 = tile * 64;
#pragma unroll
        for (int j = 0; j < 8; j++) {
            int lr = te * 8 + j;
            int r = row0 + lr;
            if (r < M)
                ((float4*)(sA + lr * H))[tc] = ((const float4*)(A + (size_t)r * H))[tc];
            else
                ((float4*)(sA + lr * H))[tc] = make_float4(0.f, 0.f, 0.f, 0.f);
        }
        __syncthreads();

        float acc[8][4];
#pragma unroll
        for (int jr = 0; jr < 8; jr++) {
            acc[jr][0] = 0.f; acc[jr][1] = 0.f; acc[jr][2] = 0.f; acc[jr][3] = 0.f;
        }
        for (int k = 0; k < H; k += 4) {
            float4 x[8];
#pragma unroll
            for (int jr = 0; jr < 8; jr++)
                x[jr] = *(const float4*)(sA + (te * 8 + jr) * H + k);
#pragma unroll
            for (int kk = 0; kk < 4; kk++) {
                float4 w = *(const float4*)(sW + (k + kk) * H + c0);
#pragma unroll
                for (int jr = 0; jr < 8; jr++) {
                    float a = ((const float*)&x[jr])[kk];
                    acc[jr][0] = fmaf(a, w.x, acc[jr][0]);
                    acc[jr][1] = fmaf(a, w.y, acc[jr][1]);
                    acc[jr][2] = fmaf(a, w.z, acc[jr][2]);
                    acc[jr][3] = fmaf(a, w.w, acc[jr][3]);
                }
            }
        }
#pragma unroll
        for (int jr = 0; jr < 8; jr++) {
            int lr = te * 8 + jr;
            int r = row0 + lr;
            if (r < M) {
                float4 o = make_float4(acc[jr][0], acc[jr][1], acc[jr][2], acc[jr][3]);
                ((float4*)(out + (size_t)r * H))[tc] = o;
            }
        }
        __syncthreads();
    }
}

// Fused edge predictor using precomputed Pu/Pr:
//   h1 = relu(Pu[src] + Pr[dst] + ea@W1c + b1); h1 = bn(h1)
//   h2 = relu(h1@W2 + b2); out = sigmoid(h2@W3 + b3)
__global__ void __launch_bounds__(256, 2)
edgepred_kernel(const int* __restrict__ utSrc, const int* __restrict__ utDst,
                const float* __restrict__ ea,
                const float* __restrict__ Pu, const float* __restrict__ Pr,
                const float* __restrict__ W1c, const float* __restrict__ b1,
                const float* __restrict__ bng, const float* __restrict__ bnb,
                const float* __restrict__ bnm, const float* __restrict__ bnv,
                const float* __restrict__ W2, const float* __restrict__ b2,
                const float* __restrict__ W3, const float* __restrict__ b3,
                float* __restrict__ outp, int E) {
    extern __shared__ float sm[];
    float* sW1c = sm;                     // 16*128 = 2048
    float* sW2 = sW1c + 2048;             // 128*64 = 8192
    float* xs = sW2 + 8192;               // 32*128 = 4096 (reused as h2 [32][65])
    float* sea = xs + 4096;               // 32*16  = 512
    float* h1 = sea + 512;                // 32*128 = 4096
    float* pb1 = h1 + 4096;               // 128
    float* ps1 = pb1 + 128;               // 128
    float* pt1 = ps1 + 128;               // 128
    float* pb2 = pt1 + 128;               // 64
    float* pW3 = pb2 + 64;                // 64
    float* pb3 = pW3 + 64;                // 1

    int tid = threadIdx.x;
    int lane = tid & 31;
    int w = tid >> 5;

    for (int i = tid; i < 2048 / 4; i += 256)
        ((float4*)sW1c)[i] = ((const float4*)W1c)[i];
    for (int i = tid; i < 8192 / 4; i += 256)
        ((float4*)sW2)[i] = ((const float4*)W2)[i];
    if (tid < 128) {
        pb1[tid] = b1[tid];
        float s = bng[tid] * rsqrtf(bnv[tid] + BN_EPS);
        ps1[tid] = s;
        pt1[tid] = bnb[tid] - bnm[tid] * s;
    } else if (tid < 192) {
        pb2[tid - 128] = b2[tid - 128];
    } else {
        pW3[tid - 192] = W3[tid - 192];
    }
    if (tid == 0) pb3[0] = b3[0];
    __syncthreads();

    int tc = tid & 31;      // layer1 col group
    int te = tid >> 5;      // layer1 edge group
    int c0 = tc * 4;
    int e0 = te * 4;
    int tc2 = tid & 15;     // layer2 col group
    int te2 = tid >> 4;     // layer2 edge group
    int cc0 = tc2 * 4;
    int ee0 = te2 * 2;

    int numTiles = E / 32;
    for (int tile = blockIdx.x; tile < numTiles; tile += gridDim.x) {
        int base = tile * 32;
        // gather: warp w loads edges w*4 .. w*4+3; xs = Pu[src] + Pr[dst]
#pragma unroll
        for (int i = 0; i < 4; i++) {
            int e = w * 4 + i;
            int eg = base + e;
            int s = utSrc[eg];
            int d = utDst[eg];
            float4 a = ((const float4*)(Pu + (size_t)s * H))[lane];
            float4 bvv = ((const float4*)(Pr + (size_t)d * H))[lane];
            a.x += bvv.x; a.y += bvv.y; a.z += bvv.z; a.w += bvv.w;
            *(float4*)(xs + e * H + lane * 4) = a;
            if (lane < 4)
                *(float4*)(sea + e * 16 + lane * 4) = ((const float4*)(ea + (size_t)eg * 16))[lane];
        }
        __syncthreads();

        // layer 1: acc = b1 + xs + sea@W1c  (K=16)
        float acc[4][4];
        {
            float4 bbv = *(const float4*)(pb1 + c0);
#pragma unroll
            for (int jr = 0; jr < 4; jr++) {
                float4 xv = *(const float4*)(xs + (e0 + jr) * H + c0);
                acc[jr][0] = bbv.x + xv.x; acc[jr][1] = bbv.y + xv.y;
                acc[jr][2] = bbv.z + xv.z; acc[jr][3] = bbv.w + xv.w;
            }
        }
#pragma unroll
        for (int k = 0; k < 16; k += 4) {
            float4 s0 = *(const float4*)(sea + (e0 + 0) * 16 + k);
            float4 s1 = *(const float4*)(sea + (e0 + 1) * 16 + k);
            float4 s2 = *(const float4*)(sea + (e0 + 2) * 16 + k);
            float4 s3 = *(const float4*)(sea + (e0 + 3) * 16 + k);
#pragma unroll
            for (int kk = 0; kk < 4; kk++) {
                float4 wv = *(const float4*)(sW1c + (k + kk) * H + c0);
                float a0 = ((const float*)&s0)[kk];
                float a1 = ((const float*)&s1)[kk];
                float a2 = ((const float*)&s2)[kk];
                float a3 = ((const float*)&s3)[kk];
                acc[0][0] = fmaf(a0, wv.x, acc[0][0]); acc[0][1] = fmaf(a0, wv.y, acc[0][1]);
                acc[0][2] = fmaf(a0, wv.z, acc[0][2]); acc[0][3] = fmaf(a0, wv.w, acc[0][3]);
                acc[1][0] = fmaf(a1, wv.x, acc[1][0]); acc[1][1] = fmaf(a1, wv.y, acc[1][1]);
                acc[1][2] = fmaf(a1, wv.z, acc[1][2]); acc[1][3] = fmaf(a1, wv.w, acc[1][3]);
                acc[2][0] = fmaf(a2, wv.x, acc[2][0]); acc[2][1] = fmaf(a2, wv.y, acc[2][1]);
                acc[2][2] = fmaf(a2, wv.z, acc[2][2]); acc[2][3] = fmaf(a2, wv.w, acc[2][3]);
                acc[3][0] = fmaf(a3, wv.x, acc[3][0]); acc[3][1] = fmaf(a3, wv.y, acc[3][1]);
                acc[3][2] = fmaf(a3, wv.z, acc[3][2]); acc[3][3] = fmaf(a3, wv.w, acc[3][3]);
            }
        }
        // relu -> BN, write h1
#pragma unroll
        for (int jr = 0; jr < 4; jr++) {
            float o[4];
#pragma unroll
            for (int jc = 0; jc < 4; jc++) {
                float z = fmaxf(acc[jr][jc], 0.0f);
                o[jc] = z * ps1[c0 + jc] + pt1[c0 + jc];
            }
            *(float4*)(h1 + (e0 + jr) * H + c0) = make_float4(o[0], o[1], o[2], o[3]);
        }
        __syncthreads();

        // layer 2: 32x64 outputs, K=128 ; h2 overwrites xs (stride 65)
        float* h2 = xs;
        {
            float a2r[2][4];
            float4 bbv = *(const float4*)(pb2 + cc0);
#pragma unroll
            for (int jr = 0; jr < 2; jr++) {
                a2r[jr][0] = bbv.x; a2r[jr][1] = bbv.y; a2r[jr][2] = bbv.z; a2r[jr][3] = bbv.w;
            }
            const float* hA = h1 + (ee0 + 0) * H;
            const float* hB = h1 + (ee0 + 1) * H;
            for (int k = 0; k < H; k += 4) {
                float4 xA = *(const float4*)(hA + k);
                float4 xB = *(const float4*)(hB + k);
#pragma unroll
                for (int kk = 0; kk < 4; kk++) {
                    float4 wv = *(const float4*)(sW2 + (k + kk) * 64 + cc0);
                    float aA = ((const float*)&xA)[kk];
                    float aB = ((const float*)&xB)[kk];
                    a2r[0][0] = fmaf(aA, wv.x, a2r[0][0]); a2r[0][1] = fmaf(aA, wv.y, a2r[0][1]);
                    a2r[0][2] = fmaf(aA, wv.z, a2r[0][2]); a2r[0][3] = fmaf(aA, wv.w, a2r[0][3]);
                    a2r[1][0] = fmaf(aB, wv.x, a2r[1][0]); a2r[1][1] = fmaf(aB, wv.y, a2r[1][1]);
                    a2r[1][2] = fmaf(aB, wv.z, a2r[1][2]); a2r[1][3] = fmaf(aB, wv.w, a2r[1][3]);
                }
            }
#pragma unroll
            for (int jr = 0; jr < 2; jr++)
#pragma unroll
                for (int jc = 0; jc < 4; jc++)
                    h2[(ee0 + jr) * 65 + cc0 + jc] = fmaxf(a2r[jr][jc], 0.0f);
        }
        __syncthreads();

        // layer 3 + sigmoid
        if (tid < 32) {
            int e = tid;
            float a = pb3[0];
#pragma unroll
            for (int k = 0; k < 64; k++) a = fmaf(h2[e * 65 + k], pW3[k], a);
            outp[base + e] = 1.0f / (1.0f + expf(-a));
        }
        __syncthreads();
    }
}

// ------------------------------- host ----------------------------------------
extern "C" void kernel_launch(void* const* d_in, const int* in_sizes, int n_in,
                              void* d_out, int out_size) {
    const float* x_user = (const float*)d_in[0];
    const float* x_recip = (const float*)d_in[1];
    const float* edge_attr = (const float*)d_in[2];
    const int* ei_ut = (const int*)d_in[3];
    const int* ei_ru = (const int*)d_in[4];
    const float* proj_uW = (const float*)d_in[5];
    const float* proj_ub = (const float*)d_in[6];
    const float* proj_rW = (const float*)d_in[7];
    const float* proj_rb = (const float*)d_in[8];
    const float* sage_Wl = (const float*)d_in[9];
    const float* sage_bl = (const float*)d_in[10];
    const float* sage_Wr = (const float*)d_in[11];
    const float* bn_g = (const float*)d_in[12];
    const float* bn_b = (const float*)d_in[13];
    const float* bn_m = (const float*)d_in[14];
    const float* bn_v = (const float*)d_in[15];
    const float* ep_W1 = (const float*)d_in[16];
    const float* ep_b1 = (const float*)d_in[17];
    const float* ep_bng = (const float*)d_in[18];
    const float* ep_bnb = (const float*)d_in[19];
    const float* ep_bnm = (const float*)d_in[20];
    const float* ep_bnv = (const float*)d_in[21];
    const float* ep_W2 = (const float*)d_in[22];
    const float* ep_b2 = (const float*)d_in[23];
    const float* ep_W3 = (const float*)d_in[24];
    const float* ep_b3 = (const float*)d_in[25];
    float* out = (float*)d_out;

    int Nu = in_sizes[0] / 32;
    int Nr = in_sizes[1] / 32;
    int E = in_sizes[3] / 2;

    const int* utSrc = ei_ut;
    const int* utDst = ei_ut + E;
    const int* ruSrc = ei_ru;
    const int* ruDst = ei_ru + E;

    float* hu; cudaGetSymbolAddress((void**)&hu, g_hu);
    float* hr; cudaGetSymbolAddress((void**)&hr, g_hr);
    float* aggR; cudaGetSymbolAddress((void**)&aggR, g_aggR);
    float* aggU; cudaGetSymbolAddress((void**)&aggU, g_aggU);
    float* cu; cudaGetSymbolAddress((void**)&cu, g_cu);
    float* cr; cudaGetSymbolAddress((void**)&cr, g_cr);

    const int G2_SMEM = (16384 * 2 + 8192 * 2 + 128 * 3) * 4;   // 198144
    const int G1_SMEM = (16384 + 8192) * 4;                     // 98304
    const int EP_SMEM = (2048 + 8192 + 4096 + 512 + 4096 + 128 * 3 + 64 + 64 + 1) * 4;
    cudaFuncSetAttribute(gemm2_kernel, cudaFuncAttributeMaxDynamicSharedMemorySize, G2_SMEM);
    cudaFuncSetAttribute(gemm1_kernel, cudaFuncAttributeMaxDynamicSharedMemorySize, G1_SMEM);
    cudaFuncSetAttribute(edgepred_kernel, cudaFuncAttributeMaxDynamicSharedMemorySize, EP_SMEM);

    const int T = 256;
    // counts (constant across layers)
    zero_kernel<<<(Nu / 4 + T - 1) / T, T>>>(cu, Nu / 4);
    zero_kernel<<<(Nr / 4 + T - 1) / T, T>>>(cr, Nr / 4);
    count_kernel<<<(E + T - 1) / T, T>>>(ruDst, E, cu);
    count_kernel<<<(E + T - 1) / T, T>>>(utDst, E, cr);
    inv_kernel<<<(Nu + T - 1) / T, T>>>(cu, Nu);
    inv_kernel<<<(Nr + T - 1) / T, T>>>(cr, Nr);

    // input projections
    proj_kernel<<<(Nu * H + T - 1) / T, T>>>(x_user, proj_uW, proj_ub, hu, Nu);
    proj_kernel<<<(Nr * H + T - 1) / T, T>>>(x_recip, proj_rW, proj_rb, hr, Nr);

    const int GRID_P = 148;
    for (int i = 0; i < 2; i++) {
        // both scatters read OLD h (before either in-place update)
        zero_kernel<<<(Nr * 32 + T - 1) / T, T>>>(aggR, Nr * 32);
        scatter_kernel<<<(E * 32 + T - 1) / T, T>>>(hu, utSrc, utDst, aggR, E);
        zero_kernel<<<(Nu * 32 + T - 1) / T, T>>>(aggU, Nu * 32);
        scatter_kernel<<<(E * 32 + T - 1) / T, T>>>(hr, ruSrc, ruDst, aggU, E);
        // in-place fused SAGE + BN + ReLU + residual
        gemm2_kernel<<<GRID_P, T, G2_SMEM>>>(aggR, cr, hr,
                                             sage_Wl + (size_t)(i * 2 + 0) * H * H,
                                             sage_Wr + (size_t)(i * 2 + 0) * H * H,
                                             sage_bl + (size_t)(i * 2 + 0) * H,
                                             bn_g + (i * 2 + 1) * H, bn_b + (i * 2 + 1) * H,
                                             bn_m + (i * 2 + 1) * H, bn_v + (i * 2 + 1) * H, Nr);
        gemm2_kernel<<<GRID_P, T, G2_SMEM>>>(aggU, cu, hu,
                                             sage_Wl + (size_t)(i * 2 + 1) * H * H,
                                             sage_Wr + (size_t)(i * 2 + 1) * H * H,
                                             sage_bl + (size_t)(i * 2 + 1) * H,
                                             bn_g + (i * 2 + 0) * H, bn_b + (i * 2 + 0) * H,
                                             bn_m + (i * 2 + 0) * H, bn_v + (i * 2 + 0) * H, Nu);
    }

    // edge predictor layer-1 decomposition: Pu = hu @ W1[0:128], Pr = hr @ W1[128:256]
    gemm1_kernel<<<2 * GRID_P, T, G1_SMEM>>>(hu, ep_W1, aggR, Nu);
    gemm1_kernel<<<2 * GRID_P, T, G1_SMEM>>>(hr, ep_W1 + 128 * H, aggU, Nr);

    edgepred_kernel<<<2 * GRID_P, T, EP_SMEM>>>(utSrc, utDst, edge_attr,
                                                aggR, aggU,
                                                ep_W1 + 256 * H, ep_b1,
                                                ep_bng, ep_bnb, ep_bnm, ep_bnv,
                                                ep_W2, ep_b2, ep_W3, ep_b3, out, E);
}

// round 4
// speedup vs baseline: 2.4461x; 1.3900x over previous
#include <cuda_runtime.h>
#include <cuda_bf16.h>
#include <math.h>

#define H 128
#define MAXN 100000
#define BN_EPS 1e-5f

// ---------------- scratch (device globals: no allocation allowed) -------------
__device__ __align__(16) float g_hu[(size_t)MAXN * H];
__device__ __align__(16) float g_hr[(size_t)MAXN * H];
__device__ __align__(16) float g_aggR[(size_t)MAXN * H];   // later reused as Pu
__device__ __align__(16) float g_aggU[(size_t)MAXN * H];   // later reused as Pr
__device__ __align__(16) float g_cu[MAXN];   // becomes 1/max(cnt,1)
__device__ __align__(16) float g_cr[MAXN];

// ---------------- small utility kernels --------------------------------------
__global__ void zero_kernel(float* __restrict__ p, int n4) {
    int i = blockIdx.x * blockDim.x + threadIdx.x;
    if (i < n4) ((float4*)p)[i] = make_float4(0.f, 0.f, 0.f, 0.f);
}

__global__ void count_kernel(const int* __restrict__ dst, int E, float* __restrict__ cnt) {
    int i = blockIdx.x * blockDim.x + threadIdx.x;
    if (i < E) atomicAdd(&cnt[dst[i]], 1.0f);
}

__global__ void inv_kernel(float* __restrict__ c, int n) {
    int i = blockIdx.x * blockDim.x + threadIdx.x;
    if (i < n) c[i] = 1.0f / fmaxf(c[i], 1.0f);
}

// y[n,H] = x[n,32] @ W[32,H] + b
__global__ void proj_kernel(const float* __restrict__ x, const float* __restrict__ W,
                            const float* __restrict__ b, float* __restrict__ y, int n) {
    int i = blockIdx.x * blockDim.x + threadIdx.x;
    if (i >= n * H) return;
    int row = i >> 7;
    int c = i & (H - 1);
    const float* xr = x + (size_t)row * 32;
    float acc = b[c];
#pragma unroll
    for (int k = 0; k < 32; k++) acc = fmaf(xr[k], W[k * H + c], acc);
    y[i] = acc;
}

// agg[dst] += hsrc[src]  using 128-bit vector reductions; 32 threads/edge
__global__ void scatter_kernel(const float* __restrict__ hsrc, const int* __restrict__ srcI,
                               const int* __restrict__ dstI, float* __restrict__ agg, int E) {
    int t = blockIdx.x * blockDim.x + threadIdx.x;
    int e = t >> 5;
    int j = t & 31;
    if (e >= E) return;
    int s = srcI[e];
    int d = dstI[e];
    float4 v = ((const float4*)(hsrc + (size_t)s * H))[j];
    float* p = agg + (size_t)d * H + j * 4;
    asm volatile("red.global.add.v4.f32 [%0], {%1, %2, %3, %4};"
                 :: "l"(p), "f"(v.x), "f"(v.y), "f"(v.z), "f"(v.w) : "memory");
}

// ------------------------ bf16 tensor-core GEMM -------------------------------
__device__ __forceinline__ void mma16816(float* d, const unsigned* a, unsigned b0, unsigned b1) {
    asm volatile("mma.sync.aligned.m16n8k16.row.col.f32.bf16.bf16.f32 "
                 "{%0,%1,%2,%3}, {%4,%5,%6,%7}, {%8,%9}, {%0,%1,%2,%3};"
                 : "+f"(d[0]), "+f"(d[1]), "+f"(d[2]), "+f"(d[3])
                 : "r"(a[0]), "r"(a[1]), "r"(a[2]), "r"(a[3]), "r"(b0), "r"(b1));
}

// MODE 0: Out = A @ W1              (K = KT*16 = 128)
// MODE 1: Bh  = relu(bn( [A*invc | Bh] @ [W1;W2] + bias )) + Bh   (K = 256)
// 128x128 output tiles, 256 threads, persistent grid.
template <int KT, int MODE>
__global__ void __launch_bounds__(256)
mma_gemm_kernel(const float* __restrict__ A, const float* __restrict__ invc,
                float* __restrict__ Bh, float* __restrict__ Out,
                const float* __restrict__ W1, const float* __restrict__ W2,
                const float* __restrict__ bias,
                const float* __restrict__ bg, const float* __restrict__ bb,
                const float* __restrict__ bm, const float* __restrict__ bv, int M) {
    constexpr int K = KT * 16;
    constexpr int KPAD = K + 8;
    extern __shared__ __align__(16) unsigned char smraw[];
    __nv_bfloat16* sWt = (__nv_bfloat16*)smraw;                 // [128][KPAD]  (n-major)
    __nv_bfloat16* sA = sWt + 128 * KPAD;                       // [128][KPAD]  (row-major)
    float* sS = (float*)(sA + 128 * KPAD);                      // 128
    float* sT = sS + 128;                                       // 128

    int tid = threadIdx.x;
    int lane = tid & 31;
    int wid = tid >> 5;
    int warp_m = wid >> 1;      // 0..3  -> 32 rows each
    int warp_n = wid & 1;       // 0..1  -> 64 cols each

    // load W transposed (n-major) as bf16
    for (int i = tid; i < K * 128; i += 256) {
        int k = i >> 7;
        int n = i & 127;
        float w = (MODE == 1 && k >= 128) ? W2[(k - 128) * 128 + n] : W1[k * 128 + n];
        sWt[n * KPAD + k] = __float2bfloat16(w);
    }
    if (MODE == 1 && tid < 128) {
        float s = bg[tid] * rsqrtf(bv[tid] + BN_EPS);
        sS[tid] = s;
        sT[tid] = (bias[tid] - bm[tid]) * s + bb[tid];
    }
    __syncthreads();

    int numTiles = (M + 127) >> 7;
    for (int tile = blockIdx.x; tile < numTiles; tile += gridDim.x) {
        int row0 = tile * 128;
        // ---- stage A tile (and Bh tile for MODE 1) as bf16 ----
        for (int i = tid; i < 128 * 32; i += 256) {
            int r = i >> 5;
            int q = i & 31;
            int row = row0 + r;
            float4 a = make_float4(0.f, 0.f, 0.f, 0.f);
            if (row < M) {
                a = ((const float4*)(A + (size_t)row * H))[q];
                if (MODE == 1) {
                    float sc = invc[row];
                    a.x *= sc; a.y *= sc; a.z *= sc; a.w *= sc;
                }
            }
            __nv_bfloat162 p0 = __floats2bfloat162_rn(a.x, a.y);
            __nv_bfloat162 p1 = __floats2bfloat162_rn(a.z, a.w);
            *(uint2*)(sA + r * KPAD + q * 4) = make_uint2(*(unsigned*)&p0, *(unsigned*)&p1);
            if (MODE == 1) {
                float4 hv = make_float4(0.f, 0.f, 0.f, 0.f);
                if (row < M) hv = ((const float4*)(Bh + (size_t)row * H))[q];
                __nv_bfloat162 q0 = __floats2bfloat162_rn(hv.x, hv.y);
                __nv_bfloat162 q1 = __floats2bfloat162_rn(hv.z, hv.w);
                *(uint2*)(sA + r * KPAD + 128 + q * 4) = make_uint2(*(unsigned*)&q0, *(unsigned*)&q1);
            }
        }
        __syncthreads();

        // ---- mma mainloop ----
        float acc[2][8][4];
#pragma unroll
        for (int mt = 0; mt < 2; mt++)
#pragma unroll
            for (int nt = 0; nt < 8; nt++)
#pragma unroll
                for (int j = 0; j < 4; j++) acc[mt][nt][j] = 0.f;

        int ar = warp_m * 32 + (lane >> 2);
        int ac = (lane & 3) * 2;
#pragma unroll
        for (int ks = 0; ks < KT; ks++) {
            int kb = ks * 16;
            unsigned a[2][4];
#pragma unroll
            for (int mt = 0; mt < 2; mt++) {
                const __nv_bfloat16* base = sA + (ar + mt * 16) * KPAD + kb + ac;
                a[mt][0] = *(const unsigned*)(base);
                a[mt][1] = *(const unsigned*)(base + 8 * KPAD);
                a[mt][2] = *(const unsigned*)(base + 8);
                a[mt][3] = *(const unsigned*)(base + 8 * KPAD + 8);
            }
#pragma unroll
            for (int nt = 0; nt < 8; nt++) {
                const __nv_bfloat16* bbase = sWt + (warp_n * 64 + nt * 8 + (lane >> 2)) * KPAD + kb + ac;
                unsigned b0 = *(const unsigned*)(bbase);
                unsigned b1 = *(const unsigned*)(bbase + 8);
                mma16816(acc[0][nt], a[0], b0, b1);
                mma16816(acc[1][nt], a[1], b0, b1);
            }
        }

        // ---- epilogue ----
        int rbase = row0 + warp_m * 32 + (lane >> 2);
        int cbase = warp_n * 64 + (lane & 3) * 2;
#pragma unroll
        for (int mt = 0; mt < 2; mt++) {
#pragma unroll
            for (int half = 0; half < 2; half++) {
                int row = rbase + mt * 16 + half * 8;
                if (row < M) {
#pragma unroll
                    for (int nt = 0; nt < 8; nt++) {
                        int c = cbase + nt * 8;
                        float v0 = acc[mt][nt][half * 2 + 0];
                        float v1 = acc[mt][nt][half * 2 + 1];
                        if (MODE == 1) {
                            v0 = v0 * sS[c] + sT[c];
                            v1 = v1 * sS[c + 1] + sT[c + 1];
                            float2 hres = *(const float2*)(Bh + (size_t)row * H + c);
                            float2 o = make_float2(fmaxf(v0, 0.f) + hres.x, fmaxf(v1, 0.f) + hres.y);
                            *(float2*)(Bh + (size_t)row * H + c) = o;
                        } else {
                            *(float2*)(Out + (size_t)row * H + c) = make_float2(v0, v1);
                        }
                    }
                }
            }
        }
        __syncthreads();
    }
}

// Fused edge predictor using precomputed Pu/Pr:
//   h1 = bn(relu(Pu[src] + Pr[dst] + ea@W1c + b1))
//   h2 = relu(h1@W2 + b2); out = sigmoid(h2@W3 + b3)
__global__ void __launch_bounds__(256, 2)
edgepred_kernel(const int* __restrict__ utSrc, const int* __restrict__ utDst,
                const float* __restrict__ ea,
                const float* __restrict__ Pu, const float* __restrict__ Pr,
                const float* __restrict__ W1c, const float* __restrict__ b1,
                const float* __restrict__ bng, const float* __restrict__ bnb,
                const float* __restrict__ bnm, const float* __restrict__ bnv,
                const float* __restrict__ W2, const float* __restrict__ b2,
                const float* __restrict__ W3, const float* __restrict__ b3,
                float* __restrict__ outp, int E) {
    extern __shared__ float sm[];
    float* sW1c = sm;                     // 16*128 = 2048
    float* sW2 = sW1c + 2048;             // 128*64 = 8192
    float* xs = sW2 + 8192;               // 32*128 = 4096 (reused as h2 [32][65])
    float* sea = xs + 4096;               // 32*16  = 512
    float* h1 = sea + 512;                // 32*128 = 4096
    float* pb1 = h1 + 4096;               // 128
    float* ps1 = pb1 + 128;               // 128
    float* pt1 = ps1 + 128;               // 128
    float* pb2 = pt1 + 128;               // 64
    float* pW3 = pb2 + 64;                // 64
    float* pb3 = pW3 + 64;                // 1

    int tid = threadIdx.x;
    int lane = tid & 31;
    int w = tid >> 5;

    for (int i = tid; i < 2048 / 4; i += 256)
        ((float4*)sW1c)[i] = ((const float4*)W1c)[i];
    for (int i = tid; i < 8192 / 4; i += 256)
        ((float4*)sW2)[i] = ((const float4*)W2)[i];
    if (tid < 128) {
        pb1[tid] = b1[tid];
        float s = bng[tid] * rsqrtf(bnv[tid] + BN_EPS);
        ps1[tid] = s;
        pt1[tid] = bnb[tid] - bnm[tid] * s;
    } else if (tid < 192) {
        pb2[tid - 128] = b2[tid - 128];
    } else {
        pW3[tid - 192] = W3[tid - 192];
    }
    if (tid == 0) pb3[0] = b3[0];
    __syncthreads();

    int tc = tid & 31;      // layer1 col group
    int te = tid >> 5;      // layer1 edge group
    int c0 = tc * 4;
    int e0 = te * 4;
    int tc2 = tid & 15;     // layer2 col group
    int te2 = tid >> 4;     // layer2 edge group
    int cc0 = tc2 * 4;
    int ee0 = te2 * 2;

    int numTiles = E / 32;
    for (int tile = blockIdx.x; tile < numTiles; tile += gridDim.x) {
        int base = tile * 32;
#pragma unroll
        for (int i = 0; i < 4; i++) {
            int e = w * 4 + i;
            int eg = base + e;
            int s = utSrc[eg];
            int d = utDst[eg];
            float4 a = ((const float4*)(Pu + (size_t)s * H))[lane];
            float4 bvv = ((const float4*)(Pr + (size_t)d * H))[lane];
            a.x += bvv.x; a.y += bvv.y; a.z += bvv.z; a.w += bvv.w;
            *(float4*)(xs + e * H + lane * 4) = a;
            if (lane < 4)
                *(float4*)(sea + e * 16 + lane * 4) = ((const float4*)(ea + (size_t)eg * 16))[lane];
        }
        __syncthreads();

        // layer 1: acc = b1 + xs + sea@W1c  (K=16)
        float acc[4][4];
        {
            float4 bbv = *(const float4*)(pb1 + c0);
#pragma unroll
            for (int jr = 0; jr < 4; jr++) {
                float4 xv = *(const float4*)(xs + (e0 + jr) * H + c0);
                acc[jr][0] = bbv.x + xv.x; acc[jr][1] = bbv.y + xv.y;
                acc[jr][2] = bbv.z + xv.z; acc[jr][3] = bbv.w + xv.w;
            }
        }
#pragma unroll
        for (int k = 0; k < 16; k += 4) {
            float4 s0 = *(const float4*)(sea + (e0 + 0) * 16 + k);
            float4 s1 = *(const float4*)(sea + (e0 + 1) * 16 + k);
            float4 s2 = *(const float4*)(sea + (e0 + 2) * 16 + k);
            float4 s3 = *(const float4*)(sea + (e0 + 3) * 16 + k);
#pragma unroll
            for (int kk = 0; kk < 4; kk++) {
                float4 wv = *(const float4*)(sW1c + (k + kk) * H + c0);
                float a0 = ((const float*)&s0)[kk];
                float a1 = ((const float*)&s1)[kk];
                float a2 = ((const float*)&s2)[kk];
                float a3 = ((const float*)&s3)[kk];
                acc[0][0] = fmaf(a0, wv.x, acc[0][0]); acc[0][1] = fmaf(a0, wv.y, acc[0][1]);
                acc[0][2] = fmaf(a0, wv.z, acc[0][2]); acc[0][3] = fmaf(a0, wv.w, acc[0][3]);
                acc[1][0] = fmaf(a1, wv.x, acc[1][0]); acc[1][1] = fmaf(a1, wv.y, acc[1][1]);
                acc[1][2] = fmaf(a1, wv.z, acc[1][2]); acc[1][3] = fmaf(a1, wv.w, acc[1][3]);
                acc[2][0] = fmaf(a2, wv.x, acc[2][0]); acc[2][1] = fmaf(a2, wv.y, acc[2][1]);
                acc[2][2] = fmaf(a2, wv.z, acc[2][2]); acc[2][3] = fmaf(a2, wv.w, acc[2][3]);
                acc[3][0] = fmaf(a3, wv.x, acc[3][0]); acc[3][1] = fmaf(a3, wv.y, acc[3][1]);
                acc[3][2] = fmaf(a3, wv.z, acc[3][2]); acc[3][3] = fmaf(a3, wv.w, acc[3][3]);
            }
        }
#pragma unroll
        for (int jr = 0; jr < 4; jr++) {
            float o[4];
#pragma unroll
            for (int jc = 0; jc < 4; jc++) {
                float z = fmaxf(acc[jr][jc], 0.0f);
                o[jc] = z * ps1[c0 + jc] + pt1[c0 + jc];
            }
            *(float4*)(h1 + (e0 + jr) * H + c0) = make_float4(o[0], o[1], o[2], o[3]);
        }
        __syncthreads();

        // layer 2: 32x64 outputs, K=128 ; h2 overwrites xs (stride 65)
        float* h2 = xs;
        {
            float a2r[2][4];
            float4 bbv = *(const float4*)(pb2 + cc0);
#pragma unroll
            for (int jr = 0; jr < 2; jr++) {
                a2r[jr][0] = bbv.x; a2r[jr][1] = bbv.y; a2r[jr][2] = bbv.z; a2r[jr][3] = bbv.w;
            }
            const float* hA = h1 + (ee0 + 0) * H;
            const float* hB = h1 + (ee0 + 1) * H;
            for (int k = 0; k < H; k += 4) {
                float4 xA = *(const float4*)(hA + k);
                float4 xB = *(const float4*)(hB + k);
#pragma unroll
                for (int kk = 0; kk < 4; kk++) {
                    float4 wv = *(const float4*)(sW2 + (k + kk) * 64 + cc0);
                    float aA = ((const float*)&xA)[kk];
                    float aB = ((const float*)&xB)[kk];
                    a2r[0][0] = fmaf(aA, wv.x, a2r[0][0]); a2r[0][1] = fmaf(aA, wv.y, a2r[0][1]);
                    a2r[0][2] = fmaf(aA, wv.z, a2r[0][2]); a2r[0][3] = fmaf(aA, wv.w, a2r[0][3]);
                    a2r[1][0] = fmaf(aB, wv.x, a2r[1][0]); a2r[1][1] = fmaf(aB, wv.y, a2r[1][1]);
                    a2r[1][2] = fmaf(aB, wv.z, a2r[1][2]); a2r[1][3] = fmaf(aB, wv.w, a2r[1][3]);
                }
            }
#pragma unroll
            for (int jr = 0; jr < 2; jr++)
#pragma unroll
                for (int jc = 0; jc < 4; jc++)
                    h2[(ee0 + jr) * 65 + cc0 + jc] = fmaxf(a2r[jr][jc], 0.0f);
        }
        __syncthreads();

        if (tid < 32) {
            int e = tid;
            float a = pb3[0];
#pragma unroll
            for (int k = 0; k < 64; k++) a = fmaf(h2[e * 65 + k], pW3[k], a);
            outp[base + e] = 1.0f / (1.0f + expf(-a));
        }
        __syncthreads();
    }
}

// ------------------------------- host ----------------------------------------
extern "C" void kernel_launch(void* const* d_in, const int* in_sizes, int n_in,
                              void* d_out, int out_size) {
    const float* x_user = (const float*)d_in[0];
    const float* x_recip = (const float*)d_in[1];
    const float* edge_attr = (const float*)d_in[2];
    const int* ei_ut = (const int*)d_in[3];
    const int* ei_ru = (const int*)d_in[4];
    const float* proj_uW = (const float*)d_in[5];
    const float* proj_ub = (const float*)d_in[6];
    const float* proj_rW = (const float*)d_in[7];
    const float* proj_rb = (const float*)d_in[8];
    const float* sage_Wl = (const float*)d_in[9];
    const float* sage_bl = (const float*)d_in[10];
    const float* sage_Wr = (const float*)d_in[11];
    const float* bn_g = (const float*)d_in[12];
    const float* bn_b = (const float*)d_in[13];
    const float* bn_m = (const float*)d_in[14];
    const float* bn_v = (const float*)d_in[15];
    const float* ep_W1 = (const float*)d_in[16];
    const float* ep_b1 = (const float*)d_in[17];
    const float* ep_bng = (const float*)d_in[18];
    const float* ep_bnb = (const float*)d_in[19];
    const float* ep_bnm = (const float*)d_in[20];
    const float* ep_bnv = (const float*)d_in[21];
    const float* ep_W2 = (const float*)d_in[22];
    const float* ep_b2 = (const float*)d_in[23];
    const float* ep_W3 = (const float*)d_in[24];
    const float* ep_b3 = (const float*)d_in[25];
    float* out = (float*)d_out;

    int Nu = in_sizes[0] / 32;
    int Nr = in_sizes[1] / 32;
    int E = in_sizes[3] / 2;

    const int* utSrc = ei_ut;
    const int* utDst = ei_ut + E;
    const int* ruSrc = ei_ru;
    const int* ruDst = ei_ru + E;

    float* hu; cudaGetSymbolAddress((void**)&hu, g_hu);
    float* hr; cudaGetSymbolAddress((void**)&hr, g_hr);
    float* aggR; cudaGetSymbolAddress((void**)&aggR, g_aggR);
    float* aggU; cudaGetSymbolAddress((void**)&aggU, g_aggU);
    float* cu; cudaGetSymbolAddress((void**)&cu, g_cu);
    float* cr; cudaGetSymbolAddress((void**)&cr, g_cr);

    // smem sizes: MODE1: 2 bf16 tiles [128][264] + 256 floats; MODE0: 2x [128][136]
    const int SM1 = (128 * 264 * 2) * 2 + 256 * 4;
    const int SM0 = (128 * 136 * 2) * 2;
    const int EP_SMEM = (2048 + 8192 + 4096 + 512 + 4096 + 128 * 3 + 64 + 64 + 1) * 4;
    cudaFuncSetAttribute(mma_gemm_kernel<16, 1>, cudaFuncAttributeMaxDynamicSharedMemorySize, SM1);
    cudaFuncSetAttribute(mma_gemm_kernel<8, 0>, cudaFuncAttributeMaxDynamicSharedMemorySize, SM0);
    cudaFuncSetAttribute(edgepred_kernel, cudaFuncAttributeMaxDynamicSharedMemorySize, EP_SMEM);

    const int T = 256;
    zero_kernel<<<(Nu / 4 + T - 1) / T, T>>>(cu, Nu / 4);
    zero_kernel<<<(Nr / 4 + T - 1) / T, T>>>(cr, Nr / 4);
    count_kernel<<<(E + T - 1) / T, T>>>(ruDst, E, cu);
    count_kernel<<<(E + T - 1) / T, T>>>(utDst, E, cr);
    inv_kernel<<<(Nu + T - 1) / T, T>>>(cu, Nu);
    inv_kernel<<<(Nr + T - 1) / T, T>>>(cr, Nr);

    proj_kernel<<<(Nu * H + T - 1) / T, T>>>(x_user, proj_uW, proj_ub, hu, Nu);
    proj_kernel<<<(Nr * H + T - 1) / T, T>>>(x_recip, proj_rW, proj_rb, hr, Nr);

    const int GRID_P = 148;
    for (int i = 0; i < 2; i++) {
        // both scatters read OLD h (before either in-place update)
        zero_kernel<<<(Nr * 32 + T - 1) / T, T>>>(aggR, Nr * 32);
        scatter_kernel<<<(E * 32 + T - 1) / T, T>>>(hu, utSrc, utDst, aggR, E);
        zero_kernel<<<(Nu * 32 + T - 1) / T, T>>>(aggU, Nu * 32);
        scatter_kernel<<<(E * 32 + T - 1) / T, T>>>(hr, ruSrc, ruDst, aggU, E);
        // fused SAGE + BN + ReLU + residual (in place on h), bf16 tensor cores
        mma_gemm_kernel<16, 1><<<GRID_P, T, SM1>>>(
            aggR, cr, hr, nullptr,
            sage_Wl + (size_t)(i * 2 + 0) * H * H, sage_Wr + (size_t)(i * 2 + 0) * H * H,
            sage_bl + (size_t)(i * 2 + 0) * H,
            bn_g + (i * 2 + 1) * H, bn_b + (i * 2 + 1) * H,
            bn_m + (i * 2 + 1) * H, bn_v + (i * 2 + 1) * H, Nr);
        mma_gemm_kernel<16, 1><<<GRID_P, T, SM1>>>(
            aggU, cu, hu, nullptr,
            sage_Wl + (size_t)(i * 2 + 1) * H * H, sage_Wr + (size_t)(i * 2 + 1) * H * H,
            sage_bl + (size_t)(i * 2 + 1) * H,
            bn_g + (i * 2 + 0) * H, bn_b + (i * 2 + 0) * H,
            bn_m + (i * 2 + 0) * H, bn_v + (i * 2 + 0) * H, Nu);
    }

    // edge predictor layer-1 decomposition: Pu = hu @ W1[0:128], Pr = hr @ W1[128:256]
    mma_gemm_kernel<8, 0><<<2 * GRID_P, T, SM0>>>(hu, nullptr, nullptr, aggR,
                                                  ep_W1, nullptr, nullptr,
                                                  nullptr, nullptr, nullptr, nullptr, Nu);
    mma_gemm_kernel<8, 0><<<2 * GRID_P, T, SM0>>>(hr, nullptr, nullptr, aggU,
                                                  ep_W1 + 128 * H, nullptr, nullptr,
                                                  nullptr, nullptr, nullptr, nullptr, Nr);

    edgepred_kernel<<<2 * GRID_P, T, EP_SMEM>>>(utSrc, utDst, edge_attr,
                                                aggR, aggU,
                                                ep_W1 + 256 * H, ep_b1,
                                                ep_bng, ep_bnb, ep_bnm, ep_bnv,
                                                ep_W2, ep_b2, ep_W3, ep_b3, out, E);
}